// round 17
// baseline (speedup 1.0000x reference)
#include <cuda_runtime.h>
#include <cuda_fp16.h>
#include <mma.h>
#include <cstdint>

using namespace nvcuda;

// Problem dims
#define BB    64
#define NN    512
#define DIN   256
#define DOUTD 256
#define DOP   64
#define MTOT  (BB*NN)      // 32768

// ---------------- scratch (static device globals) ----------------
__device__ __half g_W3[768 * 256];                    // rows 0-255: M^T | 256-511: dgf_W^T | 512-767: Wv
__device__ __half g_Woph[512 * 64];                   // rows 0-255: dgf_opW | 256-511: gat_opW
__device__ float  g_biascat[512];
__device__ __half g_Xh[(size_t)MTOT * DIN];           // half inputs
__device__ __half g_OPh[(size_t)MTOT * DOP];          // half op_emb
__device__ __half g_Yh[(size_t)MTOT * 256];           // Y = X @ M (half)
__device__ __half g_SUPh[(size_t)MTOT * 256];         // support (half)
__device__ __half g_WhvH[(size_t)MTOT * 256];         // Whv (half, row-major)
__device__ __half g_Gh[(size_t)MTOT * 512];           // gate pre-acts (half)
__device__ __half g_Sh[(size_t)BB * NN * NN];         // scores (half)
__device__ __half g_attnh[(size_t)BB * NN * NN];      // softmax(attn) half
__device__ __half g_adjh[(size_t)BB * NN * NN];       // adj half
__device__ __half g_AVh[(size_t)MTOT * 256];          // attn @ Whv (half)
__device__ __half g_ASh[(size_t)MTOT * 256];          // adj @ support (half)

// ---------------- PTX helpers ----------------
__device__ __forceinline__ uint32_t smem_u32(const void* p) {
    uint32_t a;
    asm("{ .reg .u64 t; cvta.to.shared.u64 t, %1; cvt.u32.u64 %0, t; }" : "=r"(a) : "l"(p));
    return a;
}
__device__ __forceinline__ void cp16s(uint32_t dst, const void* src) {
    asm volatile("cp.async.cg.shared.global [%0], [%1], 16;" :: "r"(dst), "l"(src));
}
template <int V> struct IC { static constexpr int value = V; };

// ---------------- merged prep (weights) + f2h (activations) ----------------
// blocks [0,256): M^T columns. blocks [256,768): weight packs. blocks [768,...): f2h of X|OP|adj.
__global__ void prep_f2h(const float* __restrict__ Wq, const float* __restrict__ Wk,
                         const float* __restrict__ a_w,
                         const float* __restrict__ dgf_W,
                         const float* __restrict__ Wv,
                         const float* __restrict__ dgf_opW,
                         const float* __restrict__ gat_opW,
                         const float* __restrict__ dgf_opb,
                         const float* __restrict__ gat_opb,
                         const float4* __restrict__ X, const float4* __restrict__ OP,
                         const float4* __restrict__ AJ,
                         __half2* __restrict__ Xh, __half2* __restrict__ OPh,
                         __half2* __restrict__ AJh,
                         int n4x, int n4o, int n4a)
{
    if (blockIdx.x < 256) {
        __shared__ float wk[256];
        const int j = blockIdx.x, i = threadIdx.x;
        wk[i] = Wk[i * 256 + j] * a_w[i] * 0.0625f;
        __syncthreads();
        float s = 0.0f;
#pragma unroll 8
        for (int m = 0; m < 256; m++) s += Wq[m * 256 + i] * wk[m];
        g_W3[j * 256 + i] = __float2half_rn(s);
    } else if (blockIdx.x < 768) {
        int idx = (blockIdx.x - 256) * blockDim.x + threadIdx.x;   // 0 .. 131071
        {   // g_W3 rows 256-767
            int r = idx >> 8, i = idx & 255;
            float v = (r < 256) ? dgf_W[i * 256 + r]            // rows 256-511: dgf_W^T
                                : Wv[(r - 256) * 256 + i];      // rows 512-767: Wv
            g_W3[(256 + r) * 256 + i] = __float2half_rn(v);
        }
        if (idx < 512 * 64) {
            int n = idx >> 6, p = idx & 63;
            float v = (n < 256) ? dgf_opW[n * 64 + p] : gat_opW[(n - 256) * 64 + p];
            g_Woph[idx] = __float2half_rn(v);
        }
        if (idx < 512) {
            g_biascat[idx] = (idx < 256) ? dgf_opb[idx] : gat_opb[idx - 256];
        }
    } else {
        int i = (blockIdx.x - 768) * blockDim.x + threadIdx.x;
        const float4* src; __half2* dst; int j;
        if (i < n4x) { src = X; dst = Xh; j = i; }
        else if ((j = i - n4x) < n4o) { src = OP; dst = OPh; }
        else { j -= n4o; if (j >= n4a) return; src = AJ; dst = AJh; }
        float4 v = src[j];
        dst[2 * j]     = __floats2half2_rn(v.x, v.y);
        dst[2 * j + 1] = __floats2half2_rn(v.z, v.w);
    }
}

// ---------------- fp16 wmma GEMM: 128x128 CTA, 4 warps (2x2), 64x64 warp tile ----------------
// 128 threads/CTA, 2 CTAs/SM, BK=64, 2-stage cp.async pipeline, ONE sync per k-tile.
// BROW=0: C = A @ B^T, B row-major [N,K] (K contiguous)
// BROW=1: C = A @ B,   B row-major [K,N] (N contiguous)
// mode 1: half -> Ch. mode 3 (H kernel): col<256 -> Ch(Yh); col<512 -> Ch2(SUPh); else -> Ch3(WhvH)
// Two-job x-split: blockIdx.x >= xsplit -> job j1 (with BROW template B1), else j0 (B0).
constexpr int BKH = 64;
constexpr int LDH = 72;                    // A / BROW0-B smem stride (halfs)
constexpr int LDB_R = 136;                 // BROW1-B smem stride (halfs)
constexpr int ASTG = 128 * LDH;            // 9216 halfs
constexpr int BSTG = 9216;                 // B stage region (BROW0:128*72=9216, BROW1:64*136=8704)
constexpr int STG1 = ASTG + BSTG;          // halfs per stage

struct GJob {
    const __half* A; const __half* B; __half* Ch;
    int lda, ldb, ldch, T, mode;
    size_t sA, sB, sCh;
};

template <int B0, int B1>
__global__ __launch_bounds__(128, 2)
void gemm_h(GJob j0, GJob j1, int xsplit, __half* Ch2, __half* Ch3)
{
    extern __shared__ __half smraw[];
    __half* sm = (__half*)(((uintptr_t)smraw + 127) & ~(uintptr_t)127);

    int bx = blockIdx.x;
    const bool second = (bx >= xsplit);
    if (second) bx -= xsplit;
    const GJob j = second ? j1 : j0;

    const __half* A = j.A + (size_t)blockIdx.z * j.sA;
    const __half* B = j.B + (size_t)blockIdx.z * j.sB;
    __half* Ch = j.Ch + (size_t)blockIdx.z * j.sCh;
    const int lda = j.lda, ldb = j.ldb, ldch = j.ldch, T = j.T, mode = j.mode;

    const int bm = blockIdx.y * 128, bn = bx * 128;
    const int tid = threadIdx.x, warp = tid >> 5;
    const int wm = (warp >> 1) * 64;       // 2 warp rows x 64
    const int wn = (warp & 1) * 64;        // 2 warp cols x 64

    auto body = [&](auto bc) {
        constexpr int BROW = decltype(bc)::value;

        wmma::fragment<wmma::accumulator, 16, 16, 16, float> acc[4][4];
#pragma unroll
        for (int i = 0; i < 4; i++)
#pragma unroll
            for (int jj = 0; jj < 4; jj++) wmma::fill_fragment(acc[i][jj], 0.0f);

        auto load_stage = [&](int s, int t) {
            __half* as = sm + (size_t)s * STG1;
            __half* bs = as + ASTG;
            const int k0 = t * BKH;
#pragma unroll
            for (int it = 0; it < 8; it++) {     // A: 128 rows x 64 halfs
                int idx = tid + it * 128;
                int rr = idx >> 3, cc = idx & 7;
                cp16s(smem_u32(as + rr * LDH + cc * 8),
                      A + (size_t)(bm + rr) * lda + k0 + cc * 8);
            }
            if (BROW == 0) {
#pragma unroll
                for (int it = 0; it < 8; it++) { // B: 128 N-rows x 64 halfs (K contig)
                    int idx = tid + it * 128;
                    int rr = idx >> 3, cc = idx & 7;
                    cp16s(smem_u32(bs + rr * LDH + cc * 8),
                          B + (size_t)(bn + rr) * ldb + k0 + cc * 8);
                }
            } else {
#pragma unroll
                for (int it = 0; it < 8; it++) { // B: 64 K-rows x 128 halfs (N contig)
                    int idx = tid + it * 128;
                    int rr = idx >> 4, cc = idx & 15;
                    cp16s(smem_u32(bs + rr * LDB_R + cc * 8),
                          B + (size_t)(k0 + rr) * ldb + bn + cc * 8);
                }
            }
            asm volatile("cp.async.commit_group;");
        };

        load_stage(0, 0);

        for (int t = 0; t < T; t++) {
            const int s = t & 1;
            // wait for tile t (the only in-flight group), then ONE collective sync.
            asm volatile("cp.async.wait_group 0;");
            __syncthreads();
            // Loads for tile t+1 write stage s^1, last computed at iter t-1; every warp
            // passed the sync above AFTER finishing that compute -> safe without a 2nd sync.
            if (t + 1 < T) load_stage(s ^ 1, t + 1);

            const __half* as = sm + (size_t)s * STG1;
            const __half* bs = as + ASTG;
#pragma unroll
            for (int kk = 0; kk < BKH; kk += 16) {
                wmma::fragment<wmma::matrix_a, 16, 16, 16, __half, wmma::row_major> af[4];
#pragma unroll
                for (int ii = 0; ii < 4; ii++)
                    wmma::load_matrix_sync(af[ii], as + (wm + 16 * ii) * LDH + kk, LDH);
                if (BROW == 0) {
                    wmma::fragment<wmma::matrix_b, 16, 16, 16, __half, wmma::col_major> bf[4];
#pragma unroll
                    for (int jj = 0; jj < 4; jj++)
                        wmma::load_matrix_sync(bf[jj], bs + (wn + 16 * jj) * LDH + kk, LDH);
#pragma unroll
                    for (int ii = 0; ii < 4; ii++)
#pragma unroll
                        for (int jj = 0; jj < 4; jj++)
                            wmma::mma_sync(acc[ii][jj], af[ii], bf[jj], acc[ii][jj]);
                } else {
                    wmma::fragment<wmma::matrix_b, 16, 16, 16, __half, wmma::row_major> bf[4];
#pragma unroll
                    for (int jj = 0; jj < 4; jj++)
                        wmma::load_matrix_sync(bf[jj], bs + kk * LDB_R + wn + 16 * jj, LDB_R);
#pragma unroll
                    for (int ii = 0; ii < 4; ii++)
#pragma unroll
                        for (int jj = 0; jj < 4; jj++)
                            wmma::mma_sync(acc[ii][jj], af[ii], bf[jj], acc[ii][jj]);
                }
            }
        }

        // ---- epilogue (all half) ----
#pragma unroll
        for (int ii = 0; ii < 4; ii++)
#pragma unroll
            for (int jj = 0; jj < 4; jj++) {
                const int row = bm + wm + 16 * ii;
                const int col = bn + wn + 16 * jj;
                wmma::fragment<wmma::accumulator, 16, 16, 16, __half> hf;
#pragma unroll
                for (int t = 0; t < hf.num_elements; t++)
                    hf.x[t] = __float2half_rn(acc[ii][jj].x[t]);
                if (mode == 1) {
                    wmma::store_matrix_sync(Ch + (size_t)row * ldch + col, hf, ldch,
                                            wmma::mem_row_major);
                } else {  // mode 3: triple half output
                    if (col < 256)
                        wmma::store_matrix_sync(Ch + (size_t)row * 256 + col, hf, 256,
                                                wmma::mem_row_major);
                    else if (col < 512)
                        wmma::store_matrix_sync(Ch2 + (size_t)row * 256 + (col - 256), hf, 256,
                                                wmma::mem_row_major);
                    else
                        wmma::store_matrix_sync(Ch3 + (size_t)row * 256 + (col - 512), hf, 256,
                                                wmma::mem_row_major);
                }
            }
    };

    if (second) body(IC<B1>{});
    else        body(IC<B0>{});
}

// ---------------- warp reductions ----------------
__device__ __forceinline__ float warp_max(float v) {
#pragma unroll
    for (int o = 16; o; o >>= 1) v = fmaxf(v, __shfl_xor_sync(0xffffffffu, v, o));
    return v;
}
__device__ __forceinline__ float warp_sum(float v) {
#pragma unroll
    for (int o = 16; o; o >>= 1) v += __shfl_xor_sync(0xffffffffu, v, o);
    return v;
}

// ------- leaky+mask+softmax: 4 rows/block, 64 thr/row, 8 cols/thread, all-half I/O -------
__global__ void softmax_kernel()
{
    __shared__ float sh[4][2];
    const int rw = threadIdx.x >> 6;
    const int t = threadIdx.x & 63;
    const int wip = (threadIdx.x >> 5) & 1;
    const size_t r = (size_t)blockIdx.x * 4 + rw;
    const int c = t * 8;

    uint4 us = *(const uint4*)(g_Sh + r * NN + c);
    uint4 ua = *(const uint4*)(g_adjh + r * NN + c);

    float v[8], aa[8];
    {
        float2 p;
        p = __half22float2(*(__half2*)&us.x); v[0] = p.x; v[1] = p.y;
        p = __half22float2(*(__half2*)&us.y); v[2] = p.x; v[3] = p.y;
        p = __half22float2(*(__half2*)&us.z); v[4] = p.x; v[5] = p.y;
        p = __half22float2(*(__half2*)&us.w); v[6] = p.x; v[7] = p.y;
        p = __half22float2(*(__half2*)&ua.x); aa[0] = p.x; aa[1] = p.y;
        p = __half22float2(*(__half2*)&ua.y); aa[2] = p.x; aa[3] = p.y;
        p = __half22float2(*(__half2*)&ua.z); aa[4] = p.x; aa[5] = p.y;
        p = __half22float2(*(__half2*)&ua.w); aa[6] = p.x; aa[7] = p.y;
    }

    float m = -1e30f;
#pragma unroll
    for (int i = 0; i < 8; i++) {
        v[i] = (v[i] >= 0.0f ? v[i] : 0.2f * v[i]) * aa[i];
        m = fmaxf(m, v[i]);
    }
    m = warp_max(m);
    if ((threadIdx.x & 31) == 0) sh[rw][wip] = m;
    __syncthreads();
    m = fmaxf(sh[rw][0], sh[rw][1]);

    float e[8], s = 0.0f;
#pragma unroll
    for (int i = 0; i < 8; i++) { e[i] = expf(v[i] - m); s += e[i]; }
    s = warp_sum(s);
    __syncthreads();
    if ((threadIdx.x & 31) == 0) sh[rw][wip] = s;
    __syncthreads();
    s = sh[rw][0] + sh[rw][1];
    float inv = 1.0f / s;

    __half2 o0 = __floats2half2_rn(e[0] * inv, e[1] * inv);
    __half2 o1 = __floats2half2_rn(e[2] * inv, e[3] * inv);
    __half2 o2 = __floats2half2_rn(e[4] * inv, e[5] * inv);
    __half2 o3 = __floats2half2_rn(e[6] * inv, e[7] * inv);
    uint4 u = make_uint4(*(unsigned*)&o0, *(unsigned*)&o1, *(unsigned*)&o2, *(unsigned*)&o3);
    *(uint4*)(g_attnh + r * NN + c) = u;
}

// ---------------- final: 4 rows/block, 64 thr/row, 4 cols/thread, half inputs ----------------
__global__ void final_kernel(const float* __restrict__ dgf_b,
                             const float* __restrict__ ln_g,
                             const float* __restrict__ ln_b,
                             float* __restrict__ out)
{
    __shared__ float sh[4][2];
    const int rw = threadIdx.x >> 6;
    const int t = threadIdx.x & 63;
    const int wip = (threadIdx.x >> 5) & 1;
    const size_t r = (size_t)blockIdx.x * 4 + rw;
    const int c = t * 4;

    uint2 usup = *(const uint2*)(g_SUPh + r * 256 + c);
    uint2 uas  = *(const uint2*)(g_ASh + r * 256 + c);
    uint2 uav  = *(const uint2*)(g_AVh + r * 256 + c);
    uint2 ug0 = *(const uint2*)(g_Gh + r * 512 + c);
    uint2 ug1 = *(const uint2*)(g_Gh + r * 512 + 256 + c);
    float4 bc0 = *(const float4*)(g_biascat + c);
    float4 bc1 = *(const float4*)(g_biascat + 256 + c);
    float4 db = *(const float4*)(dgf_b + c);
    float4 lg = *(const float4*)(ln_g + c);
    float4 lb = *(const float4*)(ln_b + c);

    float2 sa = __half22float2(*(__half2*)&usup.x);
    float2 sb = __half22float2(*(__half2*)&usup.y);
    float2 aa = __half22float2(*(__half2*)&uas.x);
    float2 ab = __half22float2(*(__half2*)&uas.y);
    float2 va = __half22float2(*(__half2*)&uav.x);
    float2 vb = __half22float2(*(__half2*)&uav.y);
    float2 g0a = __half22float2(*(__half2*)&ug0.x);
    float2 g0b = __half22float2(*(__half2*)&ug0.y);
    float2 g1a = __half22float2(*(__half2*)&ug1.x);
    float2 g1b = __half22float2(*(__half2*)&ug1.y);

    float gd0 = 1.0f / (1.0f + expf(-(g0a.x + bc0.x)));
    float gd1 = 1.0f / (1.0f + expf(-(g0a.y + bc0.y)));
    float gd2 = 1.0f / (1.0f + expf(-(g0b.x + bc0.z)));
    float gd3 = 1.0f / (1.0f + expf(-(g0b.y + bc0.w)));
    float gg0 = 1.0f / (1.0f + expf(-(g1a.x + bc1.x)));
    float gg1 = 1.0f / (1.0f + expf(-(g1a.y + bc1.y)));
    float gg2 = 1.0f / (1.0f + expf(-(g1b.x + bc1.z)));
    float gg3 = 1.0f / (1.0f + expf(-(g1b.y + bc1.w)));

    float d0 = gd0 * aa.x + sa.x + db.x;
    float d1 = gd1 * aa.y + sa.y + db.y;
    float d2 = gd2 * ab.x + sb.x + db.z;
    float d3 = gd3 * ab.y + sb.y + db.w;

    float h0 = gg0 * va.x, h1 = gg1 * va.y, h2 = gg2 * vb.x, h3 = gg3 * vb.y;

    float s = warp_sum(h0 + h1 + h2 + h3);
    if ((threadIdx.x & 31) == 0) sh[rw][wip] = s;
    __syncthreads();
    float mean = (sh[rw][0] + sh[rw][1]) * (1.0f / 256.0f);

    float e0 = h0 - mean, e1 = h1 - mean, e2 = h2 - mean, e3 = h3 - mean;
    float vs = warp_sum(e0 * e0 + e1 * e1 + e2 * e2 + e3 * e3);
    __syncthreads();
    if ((threadIdx.x & 31) == 0) sh[rw][wip] = vs;
    __syncthreads();
    float var = (sh[rw][0] + sh[rw][1]) * (1.0f / 256.0f);
    float rstd = rsqrtf(var + 1e-5f);

    float4 o;
    o.x = 0.5f * (d0 + e0 * rstd * lg.x + lb.x);
    o.y = 0.5f * (d1 + e1 * rstd * lg.y + lb.y);
    o.z = 0.5f * (d2 + e2 * rstd * lg.z + lb.z);
    o.w = 0.5f * (d3 + e3 * rstd * lg.w + lb.w);
    *(float4*)(out + r * 256 + c) = o;
}

// ---------------- launch ----------------
extern "C" void kernel_launch(void* const* d_in, const int* in_sizes, int n_in,
                              void* d_out, int out_size)
{
    const float* inputs  = (const float*)d_in[0];
    const float* adj     = (const float*)d_in[1];
    const float* op_emb  = (const float*)d_in[2];
    const float* dgf_W   = (const float*)d_in[3];
    const float* dgf_b   = (const float*)d_in[4];
    const float* dgf_opW = (const float*)d_in[5];
    const float* dgf_opb = (const float*)d_in[6];
    const float* Wk      = (const float*)d_in[7];
    const float* Wv      = (const float*)d_in[8];
    const float* Wq      = (const float*)d_in[9];
    const float* a_w     = (const float*)d_in[10];
    const float* gat_opW = (const float*)d_in[11];
    const float* gat_opb = (const float*)d_in[12];
    const float* ln_g    = (const float*)d_in[13];
    const float* ln_b    = (const float*)d_in[14];
    float* out = (float*)d_out;

    __half *W3, *Woph, *Xh, *OPh, *Yh, *SUPh, *WhvH, *Gh, *Sh, *ATTh, *ADJh, *AVh, *ASh;
    cudaGetSymbolAddress((void**)&W3,   g_W3);
    cudaGetSymbolAddress((void**)&Woph, g_Woph);
    cudaGetSymbolAddress((void**)&Xh,   g_Xh);
    cudaGetSymbolAddress((void**)&OPh,  g_OPh);
    cudaGetSymbolAddress((void**)&Yh,   g_Yh);
    cudaGetSymbolAddress((void**)&SUPh, g_SUPh);
    cudaGetSymbolAddress((void**)&WhvH, g_WhvH);
    cudaGetSymbolAddress((void**)&Gh,   g_Gh);
    cudaGetSymbolAddress((void**)&Sh,   g_Sh);
    cudaGetSymbolAddress((void**)&ATTh, g_attnh);
    cudaGetSymbolAddress((void**)&ADJh, g_adjh);
    cudaGetSymbolAddress((void**)&AVh,  g_AVh);
    cudaGetSymbolAddress((void**)&ASh,  g_ASh);

    const int DSMEM = 2 * STG1 * (int)sizeof(__half) + 256;   // 2 stages, ~74KB
    cudaFuncSetAttribute(gemm_h<0,0>, cudaFuncAttributeMaxDynamicSharedMemorySize, DSMEM);
    cudaFuncSetAttribute(gemm_h<0,1>, cudaFuncAttributeMaxDynamicSharedMemorySize, DSMEM);
    cudaFuncSetAttribute(gemm_h<1,1>, cudaFuncAttributeMaxDynamicSharedMemorySize, DSMEM);

    // merged weight prep + f2h
    {
        int n4x = MTOT * DIN / 4, n4o = MTOT * DOP / 4, n4a = BB * NN * NN / 4;
        int f2h_blocks = (n4x + n4o + n4a + 255) / 256;
        prep_f2h<<<768 + f2h_blocks, 256>>>(Wq, Wk, a_w, dgf_W, Wv, dgf_opW, gat_opW,
                                            dgf_opb, gat_opb,
                                            (const float4*)inputs, (const float4*)op_emb,
                                            (const float4*)adj,
                                            (__half2*)Xh, (__half2*)OPh, (__half2*)ADJh,
                                            n4x, n4o, n4a);
    }

    // merged H + gates (both BROW=0):
    //   x<6: H = X @ [M|dgf_W|Wv]^T -> Yh | SUPh | WhvH (mode 3, T=4)
    //   x>=6: gates = OPh @ Woph^T -> Gh (mode 1, T=1, ldch=512)
    {
        GJob jH  = { Xh,  W3,   Yh, 256, 256, 256, 4, 3, 0, 0, 0 };
        GJob jG  = { OPh, Woph, Gh,  64,  64, 512, 1, 1, 0, 0, 0 };
        dim3 grid(10, MTOT / 128, 1);
        gemm_h<0,0><<<grid, 128, DSMEM>>>(jH, jG, 6, SUPh, WhvH);
    }
    // merged scores (BROW=0) + AS (BROW=1):
    //   x<4: Sh[b] = Y[b] @ X[b]^T (T=4)
    //   x>=4: ASh[b] = adjh[b] @ SUPh[b] (T=8)
    {
        GJob jS  = { Yh,   Xh,   Sh,  256, 256, 512, 4, 1,
                     (size_t)512 * 256, (size_t)512 * 256, (size_t)512 * 512 };
        GJob jAS = { ADJh, SUPh, ASh, 512, 256, 256, 8, 1,
                     (size_t)512 * 512, (size_t)512 * 256, (size_t)512 * 256 };
        dim3 grid(6, 4, BB);
        gemm_h<0,1><<<grid, 128, DSMEM>>>(jS, jAS, 4, SUPh, WhvH);
    }
    // leaky + mask + softmax -> attn half (reads Sh + adjh)
    softmax_kernel<<<MTOT / 4, 256>>>();

    // AV[b] = attn[b] @ Whv[b] (BROW=1) -> half [512,256]
    {
        GJob jAV = { ATTh, WhvH, AVh, 512, 256, 256, 8, 1,
                     (size_t)512 * 512, (size_t)512 * 256, (size_t)512 * 256 };
        dim3 grid(2, 4, BB);
        gemm_h<1,1><<<grid, 128, DSMEM>>>(jAV, jAV, 1 << 30, SUPh, WhvH);
    }
    // gates + residual + LN + blend
    final_kernel<<<MTOT / 4, 256>>>(dgf_b, ln_g, ln_b, out);

    (void)in_sizes; (void)n_in; (void)out_size;
}